// round 9
// baseline (speedup 1.0000x reference)
#include <cuda_runtime.h>
#include <cuda_bf16.h>

#define NNODE 100000
#define DEG   8
#define FIN   128
#define FB    64
#define FO    128
#define NE    (NNODE*DEG)

typedef unsigned long long u64;

__device__ __forceinline__ u64 pack2(float x){
    u64 r; asm("mov.b64 %0, {%1, %1};" : "=l"(r) : "f"(x)); return r;
}
__device__ __forceinline__ void fma2(u64 &d, u64 a, u64 b){
    asm("fma.rn.f32x2 %0, %1, %2, %0;" : "+l"(d) : "l"(a), "l"(b));
}
__device__ __forceinline__ float lo32(u64 v){ return __uint_as_float((unsigned)v); }
__device__ __forceinline__ float hi32(u64 v){ return __uint_as_float((unsigned)(v >> 32)); }

// ---------------- scratch (device globals; no runtime alloc) ----------------
__device__ float g_pre2[NNODE*FO];   // atom @ W2a^T  (no bias)
__device__ float g_nt  [NNODE*FO];   // attend(h1)
__device__ float g_h1  [NNODE*FO];   // fallback h1 storage
__device__ float g_alpha[NNODE];     // h1 . Ww[:128]
__device__ float g_W1T [FIN*FO];     // [k][o]
__device__ float g_WaT [FO*FO];
__device__ float g_W2aT[FIN*FO];
__device__ float g_W2bT[FB*FO];
__device__ float g_WihT[FO*384];     // [k][o], o in 0..383 (r,z,n)
__device__ float g_WhhT[FO*384];

// ---------------- weight prep (transposes) ----------------
__global__ void prep_weights(const float* __restrict__ W1, const float* __restrict__ Wa,
                             const float* __restrict__ W2,
                             const float* __restrict__ Wih, const float* __restrict__ Whh){
    int idx = blockIdx.x * 256 + threadIdx.x;
    if (idx < 128*128){
        int o = idx >> 7, k = idx & 127;
        g_W1T[k*128 + o] = W1[idx];
        g_WaT[k*128 + o] = Wa[idx];
    }
    if (idx < 128*192){
        int o = idx / 192, k = idx - o*192;
        float v = W2[idx];
        if (k < 128) g_W2aT[k*128 + o] = v;
        else         g_W2bT[(k-128)*128 + o] = v;
    }
    if (idx < 384*128){
        int o = idx >> 7, k = idx & 127;
        g_WihT[k*384 + o] = Wih[idx];
        g_WhhT[k*384 + o] = Whh[idx];
    }
}

// 16-pair (32 item) f32x2 GEMV accumulation: acc[p] += WT[k][t] * s[k][2p..2p+1]
__device__ __forceinline__ void gemv16(const float* __restrict__ WT, const float* __restrict__ s,
                                       int t, int K, u64 acc[16]){
    #pragma unroll 4
    for (int k = 0; k < K; k++){
        u64 w = pack2(WT[k*128 + t]);
        const float* row = s + k*34;
        #pragma unroll
        for (int p = 0; p < 16; p++)
            fma2(acc[p], w, *(const u64*)(row + 2*p));
    }
}

// ---------------- kernel 1: per-node transforms ----------------
// 32 nodes / block, 128 threads. Computes pre2, h1 (+store), nt, alpha.
__global__ void __launch_bounds__(128) node_kernel(const float* __restrict__ atom,
                                                   const float* __restrict__ b1,
                                                   const float* __restrict__ ba,
                                                   const float* __restrict__ Ww,
                                                   float* __restrict__ h1_out){
    __shared__ __align__(8) float a_s[128*34];   // [k][node], pitch 34
    __shared__ __align__(8) float h_s[128*34];
    const int t  = threadIdx.x;
    const int n0 = blockIdx.x * 32;

    for (int idx = t; idx < 32*128; idx += 128){
        int i = idx >> 7, k = idx & 127;
        a_s[k*34 + i] = atom[(n0 + i)*128 + k];
    }
    __syncthreads();

    // pre2 = atom @ W2a^T
    {
        u64 acc[16];
        #pragma unroll
        for (int p = 0; p < 16; p++) acc[p] = 0ull;
        gemv16(g_W2aT, a_s, t, 128, acc);
        #pragma unroll
        for (int p = 0; p < 16; p++){
            g_pre2[(n0 + 2*p    )*128 + t] = lo32(acc[p]);
            g_pre2[(n0 + 2*p + 1)*128 + t] = hi32(acc[p]);
        }
    }
    // h1 = lrelu(atom @ W1^T + b1)
    {
        u64 acc[16];
        #pragma unroll
        for (int p = 0; p < 16; p++) acc[p] = 0ull;
        gemv16(g_W1T, a_s, t, 128, acc);
        float bb = b1[t];
        #pragma unroll
        for (int p = 0; p < 16; p++){
            float x0 = lo32(acc[p]) + bb; x0 = x0 > 0.f ? x0 : 0.2f*x0;
            float x1 = hi32(acc[p]) + bb; x1 = x1 > 0.f ? x1 : 0.2f*x1;
            h1_out[(n0 + 2*p    )*128 + t] = x0;
            h1_out[(n0 + 2*p + 1)*128 + t] = x1;
            h_s[t*34 + 2*p    ] = x0;
            h_s[t*34 + 2*p + 1] = x1;
        }
    }
    __syncthreads();
    // nt = h1 @ Wa^T + ba
    {
        u64 acc[16];
        #pragma unroll
        for (int p = 0; p < 16; p++) acc[p] = 0ull;
        gemv16(g_WaT, h_s, t, 128, acc);
        float bb = ba[t];
        #pragma unroll
        for (int p = 0; p < 16; p++){
            g_nt[(n0 + 2*p    )*128 + t] = lo32(acc[p]) + bb;
            g_nt[(n0 + 2*p + 1)*128 + t] = hi32(acc[p]) + bb;
        }
    }
    // alpha[n] = h1[n] . Ww[:128]
    if (t < 32){
        float s = 0.f;
        #pragma unroll 4
        for (int k = 0; k < 128; k++) s += Ww[k] * h_s[k*34 + t];
        g_alpha[n0 + t] = s;
    }
}

// ---------------- kernel 2: edges + softmax + aggregate + GRU ----------------
// 16 nodes = 128 edges / block, 128 threads (thread = feature index).
__global__ void __launch_bounds__(128) edge_kernel(const float* __restrict__ bond,
                                                   const int*   __restrict__ src,
                                                   const float* __restrict__ b2,
                                                   const float* __restrict__ Ww,
                                                   const float* __restrict__ bw,
                                                   const float* __restrict__ b_ih,
                                                   const float* __restrict__ b_hh,
                                                   const float* __restrict__ h1_in,
                                                   float* __restrict__ final_out){
    const int t    = threadIdx.x;
    const int lane = t & 31;
    const int warp = t >> 5;
    const int n0   = blockIdx.x * 16;
    const int e0   = n0 * DEG;

    __shared__ __align__(8) float bond_s[64*34];   // [k][edge-in-chunk], pitch 34
    __shared__ __align__(8) float ctx_s[128*18];   // [k][node], pitch 18
    __shared__ __align__(8) float h_s  [128*18];
    __shared__ float beta_s[128];
    __shared__ float score_s[128];
    __shared__ float red_s[128];
    __shared__ int   src_s[128];

    src_s[t] = src[e0 + t];
    const float wbt = Ww[128 + t];
    const float b2t = b2[t];

    // ---- beta per edge, 4 chunks of 32 edges ----
    for (int c = 0; c < 4; c++){
        __syncthreads();
        for (int idx = t; idx < 32*64; idx += 128){
            int j = idx >> 6, k = idx & 63;
            bond_s[k*34 + j] = bond[(size_t)(e0 + c*32 + j)*64 + k];
        }
        __syncthreads();

        u64 acc[16];
        #pragma unroll
        for (int p = 0; p < 16; p++) acc[p] = 0ull;
        gemv16(g_W2bT, bond_s, t, 64, acc);

        float vals[32];
        #pragma unroll
        for (int p = 0; p < 16; p++){
            int j0 = 2*p;
            {
                float u = lo32(acc[p]) + g_pre2[src_s[c*32 + j0]*128 + t] + b2t;
                u = u > 0.f ? u : 0.2f*u;
                vals[j0] = wbt * u;
            }
            {
                float u = hi32(acc[p]) + g_pre2[src_s[c*32 + j0 + 1]*128 + t] + b2t;
                u = u > 0.f ? u : 0.2f*u;
                vals[j0 + 1] = wbt * u;
            }
        }
        // butterfly: sum each edge's value over the 32 lanes
        #pragma unroll
        for (int off = 16; off > 0; off >>= 1){
            #pragma unroll
            for (int j = 0; j < 32; j++)
                vals[j] += __shfl_xor_sync(0xffffffffu, vals[j], off);
        }
        float mine = vals[0];
        #pragma unroll
        for (int j = 1; j < 32; j++) if (lane == j) mine = vals[j];
        red_s[warp*32 + lane] = mine;
        __syncthreads();
        if (t < 32)
            beta_s[c*32 + t] = red_s[t] + red_s[32 + t] + red_s[64 + t] + red_s[96 + t];
    }

    // stage h1 tile [k=t][node]
    #pragma unroll
    for (int i = 0; i < 16; i++) h_s[t*18 + i] = h1_in[(n0 + i)*128 + t];
    __syncthreads();

    // ---- per-node softmax over 8 edges ----
    if (t < 16){
        float al = g_alpha[n0 + t] + bw[0];
        float lg[8]; float m = -3.0e38f;
        #pragma unroll
        for (int e = 0; e < 8; e++){
            float x = al + beta_s[t*8 + e];
            x = x > 0.f ? x : 0.2f*x;
            lg[e] = x; m = fmaxf(m, x);
        }
        float s = 0.f;
        #pragma unroll
        for (int e = 0; e < 8; e++){ float ex = expf(lg[e] - m); score_s[t*8 + e] = ex; s += ex; }
        float inv = 1.0f / s;
        #pragma unroll
        for (int e = 0; e < 8; e++) score_s[t*8 + e] *= inv;
    }
    __syncthreads();

    // ---- weighted gather of nt, ELU -> context ----
    #pragma unroll
    for (int i = 0; i < 16; i++){
        float a = 0.f;
        #pragma unroll
        for (int e = 0; e < 8; e++)
            a += score_s[i*8 + e] * g_nt[src_s[i*8 + e]*128 + t];
        ctx_s[t*18 + i] = a > 0.f ? a : (expf(a) - 1.0f);
    }
    __syncthreads();

    // ---- GRU: all 6 gate GEMVs in one k-loop (weights streamed once) ----
    u64 air[8], aiz[8], ain[8], ahr[8], ahz[8], ahn[8];
    #pragma unroll
    for (int p = 0; p < 8; p++){ air[p]=0; aiz[p]=0; ain[p]=0; ahr[p]=0; ahz[p]=0; ahn[p]=0; }

    #pragma unroll 2
    for (int k = 0; k < 128; k++){
        const float* wi = g_WihT + k*384 + t;
        const float* wh = g_WhhT + k*384 + t;
        u64 wir = pack2(wi[0]),   wiz = pack2(wi[128]), win = pack2(wi[256]);
        u64 whr = pack2(wh[0]),   whz = pack2(wh[128]), whn = pack2(wh[256]);
        const float* cr = ctx_s + k*18;
        const float* hr = h_s   + k*18;
        #pragma unroll
        for (int p = 0; p < 8; p++){
            u64 cx = *(const u64*)(cr + 2*p);
            u64 hx = *(const u64*)(hr + 2*p);
            fma2(air[p], wir, cx); fma2(aiz[p], wiz, cx); fma2(ain[p], win, cx);
            fma2(ahr[p], whr, hx); fma2(ahz[p], whz, hx); fma2(ahn[p], whn, hx);
        }
    }

    const float bir = b_ih[t], biz = b_ih[128 + t], binn = b_ih[256 + t];
    const float bhr = b_hh[t], bhz = b_hh[128 + t], bhn  = b_hh[256 + t];
    #pragma unroll
    for (int p = 0; p < 8; p++){
        #pragma unroll
        for (int hlf = 0; hlf < 2; hlf++){
            int i = 2*p + hlf;
            float ir = hlf ? hi32(air[p]) : lo32(air[p]);
            float iz = hlf ? hi32(aiz[p]) : lo32(aiz[p]);
            float in_= hlf ? hi32(ain[p]) : lo32(ain[p]);
            float hr_= hlf ? hi32(ahr[p]) : lo32(ahr[p]);
            float hz = hlf ? hi32(ahz[p]) : lo32(ahz[p]);
            float hn = hlf ? hi32(ahn[p]) : lo32(ahn[p]);
            float r = 1.0f / (1.0f + expf(-(ir + bir + hr_ + bhr)));
            float z = 1.0f / (1.0f + expf(-(iz + biz + hz + bhz)));
            float nn = tanhf(in_ + binn + r * (hn + bhn));
            float h  = h_s[t*18 + i];
            final_out[(n0 + i)*128 + t] = (1.0f - z)*nn + z*h;
        }
    }
}

extern "C" void kernel_launch(void* const* d_in, const int* in_sizes, int n_in,
                              void* d_out, int out_size){
    const float* atom = (const float*)d_in[0];
    const float* bond = (const float*)d_in[1];
    const int*   src  = (const int*)  d_in[2];
    // d_in[3] = dst (structurally repeat(arange(N),8); not needed)
    const float* W1  = (const float*)d_in[4];
    const float* b1  = (const float*)d_in[5];
    const float* W2  = (const float*)d_in[6];
    const float* b2  = (const float*)d_in[7];
    const float* Wa  = (const float*)d_in[8];
    const float* ba  = (const float*)d_in[9];
    const float* Ww  = (const float*)d_in[10];
    const float* bw  = (const float*)d_in[11];
    const float* Wih = (const float*)d_in[12];
    const float* bih = (const float*)d_in[13];
    const float* Whh = (const float*)d_in[14];
    const float* bhh = (const float*)d_in[15];
    float* out = (float*)d_out;

    // h1 is the 2nd output; if the harness only sized d_out for `final`,
    // keep h1 in scratch.
    float* h1_out;
    if (out_size >= 2*NNODE*FO){
        h1_out = out + (size_t)NNODE*FO;
    } else {
        void* p = nullptr;
        cudaGetSymbolAddress(&p, g_h1);
        h1_out = (float*)p;
    }

    prep_weights<<<192, 256>>>(W1, Wa, W2, Wih, Whh);
    node_kernel<<<NNODE/32, 128>>>(atom, b1, ba, Ww, h1_out);
    edge_kernel<<<NNODE/16, 128>>>(bond, src, b2, Ww, bw, bih, bhh, h1_out, out);
}

// round 10
// speedup vs baseline: 1.0377x; 1.0377x over previous
#include <cuda_runtime.h>
#include <cuda_bf16.h>

#define NNODE 100000
#define DEG   8
#define FIN   128
#define FB    64
#define FO    128
#define NE    (NNODE*DEG)

typedef unsigned long long u64;

__device__ __forceinline__ u64 pack2(float x){
    u64 r; asm("mov.b64 %0, {%1, %1};" : "=l"(r) : "f"(x)); return r;
}
__device__ __forceinline__ void fma2(u64 &d, u64 a, u64 b){
    asm("fma.rn.f32x2 %0, %1, %2, %0;" : "+l"(d) : "l"(a), "l"(b));
}
__device__ __forceinline__ float lo32(u64 v){ return __uint_as_float((unsigned)v); }
__device__ __forceinline__ float hi32(u64 v){ return __uint_as_float((unsigned)(v >> 32)); }

__device__ __forceinline__ float sigmoidf_fast(float x){
    return __fdividef(1.0f, 1.0f + __expf(-x));
}
__device__ __forceinline__ float tanhf_fast(float x){
    // 1 - 2/(e^{2x}+1); exact limits at +/-inf via fast rcp
    return 1.0f - 2.0f * __fdividef(1.0f, __expf(2.0f * x) + 1.0f);
}

// ---------------- scratch (device globals; no runtime alloc) ----------------
__device__ float g_pre2[NNODE*FO];   // atom @ W2a^T  (no bias)
__device__ float g_nt  [NNODE*FO];   // attend(h1)
__device__ float g_h1  [NNODE*FO];   // fallback h1 storage
__device__ float g_alpha[NNODE];     // h1 . Ww[:128]
// packed (duplicated f32x2) weights, [k][o] layout
__device__ u64   g_W21P[FIN*FO*2];   // interleaved: [k*128+o]*2 + {0:W2a, 1:W1}
__device__ u64   g_WaP [FO*FO];
__device__ u64   g_W2bP[FB*FO];
// GRU weights, fp32, per (k,t): A = (wir,wiz,win,whr), B = (whz,whn)
__device__ float g_WgA[FO*FO*4];
__device__ float g_WgB[FO*FO*2];

// ---------------- weight prep ----------------
__global__ void prep_weights(const float* __restrict__ W1, const float* __restrict__ Wa,
                             const float* __restrict__ W2,
                             const float* __restrict__ Wih, const float* __restrict__ Whh){
    int idx = blockIdx.x * 256 + threadIdx.x;
    if (idx < 128*128){
        int o = idx >> 7, k = idx & 127;
        g_W21P[(k*128 + o)*2 + 1] = pack2(W1[idx]);
        g_WaP [k*128 + o]         = pack2(Wa[idx]);
    }
    if (idx < 128*192){
        int o = idx / 192, k = idx - o*192;
        float v = W2[idx];
        if (k < 128) g_W21P[(k*128 + o)*2 + 0] = pack2(v);
        else         g_W2bP[(k-128)*128 + o]   = pack2(v);
    }
    if (idx < 384*128){
        int o = idx >> 7, k = idx & 127;
        int t = o & 127, g = o >> 7;
        float vi = Wih[idx], vh = Whh[idx];
        int b4 = (k*128 + t)*4;
        int b2i = (k*128 + t)*2;
        if (g == 0){      g_WgA[b4 + 0] = vi; g_WgA[b4 + 3] = vh; }
        else if (g == 1){ g_WgA[b4 + 1] = vi; g_WgB[b2i + 0] = vh; }
        else {            g_WgA[b4 + 2] = vi; g_WgB[b2i + 1] = vh; }
    }
}

// ---------------- kernel 1: per-node transforms ----------------
// 32 nodes / block, 128 threads. Fused pre2+h1 GEMVs, then nt, alpha.
__global__ void __launch_bounds__(128) node_kernel(const float* __restrict__ atom,
                                                   const float* __restrict__ b1,
                                                   const float* __restrict__ ba,
                                                   const float* __restrict__ Ww,
                                                   float* __restrict__ h1_out){
    __shared__ __align__(16) float a_s[128*36];   // [k][node], pitch 36 (16B-aligned rows)
    __shared__ __align__(16) float h_s[128*36];
    const int t  = threadIdx.x;
    const int n0 = blockIdx.x * 32;

    for (int idx = t; idx < 32*128; idx += 128){
        int i = idx >> 7, k = idx & 127;
        a_s[k*36 + i] = atom[(size_t)(n0 + i)*128 + k];
    }
    __syncthreads();

    // fused: pre2 = atom @ W2a^T   and   h1pre = atom @ W1^T
    {
        u64 acc2[16], acc1[16];
        #pragma unroll
        for (int p = 0; p < 16; p++){ acc2[p] = 0ull; acc1[p] = 0ull; }
        #pragma unroll 2
        for (int k = 0; k < 128; k++){
            const ulonglong2* row = (const ulonglong2*)(a_s + k*36);
            ulonglong2 w = *(const ulonglong2*)(g_W21P + (size_t)(k*128 + t)*2);
            #pragma unroll
            for (int q = 0; q < 8; q++){
                ulonglong2 v = row[q];
                fma2(acc2[2*q  ], w.x, v.x); fma2(acc2[2*q+1], w.x, v.y);
                fma2(acc1[2*q  ], w.y, v.x); fma2(acc1[2*q+1], w.y, v.y);
            }
        }
        #pragma unroll
        for (int p = 0; p < 16; p++){
            g_pre2[(n0 + 2*p    )*128 + t] = lo32(acc2[p]);
            g_pre2[(n0 + 2*p + 1)*128 + t] = hi32(acc2[p]);
        }
        float bb = b1[t];
        #pragma unroll
        for (int p = 0; p < 16; p++){
            float x0 = lo32(acc1[p]) + bb; x0 = x0 > 0.f ? x0 : 0.2f*x0;
            float x1 = hi32(acc1[p]) + bb; x1 = x1 > 0.f ? x1 : 0.2f*x1;
            h1_out[(n0 + 2*p    )*128 + t] = x0;
            h1_out[(n0 + 2*p + 1)*128 + t] = x1;
            h_s[t*36 + 2*p    ] = x0;
            h_s[t*36 + 2*p + 1] = x1;
        }
    }
    __syncthreads();

    // nt = h1 @ Wa^T + ba
    {
        u64 acc[16];
        #pragma unroll
        for (int p = 0; p < 16; p++) acc[p] = 0ull;
        #pragma unroll 2
        for (int k = 0; k < 128; k++){
            const ulonglong2* row = (const ulonglong2*)(h_s + k*36);
            u64 w = g_WaP[k*128 + t];
            #pragma unroll
            for (int q = 0; q < 8; q++){
                ulonglong2 v = row[q];
                fma2(acc[2*q], w, v.x); fma2(acc[2*q+1], w, v.y);
            }
        }
        float bb = ba[t];
        #pragma unroll
        for (int p = 0; p < 16; p++){
            g_nt[(n0 + 2*p    )*128 + t] = lo32(acc[p]) + bb;
            g_nt[(n0 + 2*p + 1)*128 + t] = hi32(acc[p]) + bb;
        }
    }
    // alpha[n] = h1[n] . Ww[:128]
    if (t < 32){
        float s = 0.f;
        #pragma unroll 4
        for (int k = 0; k < 128; k++) s += Ww[k] * h_s[k*36 + t];
        g_alpha[n0 + t] = s;
    }
}

// ---------------- kernel 2: edges + softmax + aggregate + GRU ----------------
// 16 nodes = 128 edges / block, 128 threads (thread = feature index).
__global__ void __launch_bounds__(128) edge_kernel(const float* __restrict__ bond,
                                                   const int*   __restrict__ src,
                                                   const float* __restrict__ b2,
                                                   const float* __restrict__ Ww,
                                                   const float* __restrict__ bw,
                                                   const float* __restrict__ b_ih,
                                                   const float* __restrict__ b_hh,
                                                   const float* __restrict__ h1_in,
                                                   float* __restrict__ final_out){
    const int t    = threadIdx.x;
    const int lane = t & 31;
    const int warp = t >> 5;
    const int n0   = blockIdx.x * 16;
    const int e0   = n0 * DEG;

    __shared__ __align__(16) float bond_s[64*36];   // [k][edge-in-chunk], pitch 36
    __shared__ __align__(16) float ctx_s[128*20];   // [k][node], pitch 20
    __shared__ __align__(16) float h_s  [128*20];
    __shared__ float beta_s[128];
    __shared__ float score_s[128];
    __shared__ float red_s[128];
    __shared__ int   src_s[128];

    src_s[t] = src[e0 + t];
    const float wbt = Ww[128 + t];
    const float b2t = b2[t];

    // ---- beta per edge, 4 chunks of 32 edges ----
    for (int c = 0; c < 4; c++){
        __syncthreads();
        for (int idx = t; idx < 32*64; idx += 128){
            int j = idx >> 6, k = idx & 63;
            bond_s[k*36 + j] = bond[(size_t)(e0 + c*32 + j)*64 + k];
        }
        __syncthreads();

        u64 acc[16];
        #pragma unroll
        for (int p = 0; p < 16; p++) acc[p] = 0ull;
        #pragma unroll 2
        for (int k = 0; k < 64; k++){
            const ulonglong2* row = (const ulonglong2*)(bond_s + k*36);
            u64 w = g_W2bP[k*128 + t];
            #pragma unroll
            for (int q = 0; q < 8; q++){
                ulonglong2 v = row[q];
                fma2(acc[2*q], w, v.x); fma2(acc[2*q+1], w, v.y);
            }
        }

        float vals[32];
        #pragma unroll
        for (int p = 0; p < 16; p++){
            int j0 = 2*p;
            {
                float u = lo32(acc[p]) + g_pre2[(size_t)src_s[c*32 + j0]*128 + t] + b2t;
                u = u > 0.f ? u : 0.2f*u;
                vals[j0] = wbt * u;
            }
            {
                float u = hi32(acc[p]) + g_pre2[(size_t)src_s[c*32 + j0 + 1]*128 + t] + b2t;
                u = u > 0.f ? u : 0.2f*u;
                vals[j0 + 1] = wbt * u;
            }
        }
        // log-step transpose-reduce: after 5 stages, vals[0] on lane L =
        // sum over all 32 lanes of original vals[L].
        #pragma unroll
        for (int off = 16; off >= 1; off >>= 1){
            bool up = (lane & off) != 0;
            #pragma unroll
            for (int j = 0; j < off; j++){
                float keep = up ? vals[j + off] : vals[j];
                float send = up ? vals[j]       : vals[j + off];
                vals[j] = keep + __shfl_xor_sync(0xffffffffu, send, off);
            }
        }
        red_s[warp*32 + lane] = vals[0];
        __syncthreads();
        if (t < 32)
            beta_s[c*32 + t] = red_s[t] + red_s[32 + t] + red_s[64 + t] + red_s[96 + t];
    }

    // stage h1 tile [k=t][node]
    #pragma unroll
    for (int i = 0; i < 16; i++) h_s[t*20 + i] = h1_in[(size_t)(n0 + i)*128 + t];
    __syncthreads();

    // ---- per-node softmax over 8 edges ----
    if (t < 16){
        float al = g_alpha[n0 + t] + bw[0];
        float lg[8]; float m = -3.0e38f;
        #pragma unroll
        for (int e = 0; e < 8; e++){
            float x = al + beta_s[t*8 + e];
            x = x > 0.f ? x : 0.2f*x;
            lg[e] = x; m = fmaxf(m, x);
        }
        float s = 0.f;
        #pragma unroll
        for (int e = 0; e < 8; e++){ float ex = __expf(lg[e] - m); score_s[t*8 + e] = ex; s += ex; }
        float inv = __fdividef(1.0f, s);
        #pragma unroll
        for (int e = 0; e < 8; e++) score_s[t*8 + e] *= inv;
    }
    __syncthreads();

    // ---- weighted gather of nt, ELU -> context ----
    #pragma unroll
    for (int i = 0; i < 16; i++){
        float a = 0.f;
        #pragma unroll
        for (int e = 0; e < 8; e++)
            a += score_s[i*8 + e] * g_nt[(size_t)src_s[i*8 + e]*128 + t];
        ctx_s[t*20 + i] = a > 0.f ? a : (__expf(a) - 1.0f);
    }
    __syncthreads();

    // ---- GRU: all 6 gate GEMVs in one k-loop ----
    u64 air[8], aiz[8], ain[8], ahr[8], ahz[8], ahn[8];
    #pragma unroll
    for (int p = 0; p < 8; p++){ air[p]=0; aiz[p]=0; ain[p]=0; ahr[p]=0; ahz[p]=0; ahn[p]=0; }

    #pragma unroll 2
    for (int k = 0; k < 128; k++){
        float4 A = *(const float4*)(g_WgA + (size_t)(k*128 + t)*4);
        float2 B = *(const float2*)(g_WgB + (size_t)(k*128 + t)*2);
        u64 wir = pack2(A.x), wiz = pack2(A.y), win = pack2(A.z);
        u64 whr = pack2(A.w), whz = pack2(B.x), whn = pack2(B.y);
        const ulonglong2* cr = (const ulonglong2*)(ctx_s + k*20);
        const ulonglong2* hh = (const ulonglong2*)(h_s   + k*20);
        #pragma unroll
        for (int q = 0; q < 4; q++){
            ulonglong2 cv = cr[q];
            ulonglong2 hv = hh[q];
            fma2(air[2*q  ], wir, cv.x); fma2(air[2*q+1], wir, cv.y);
            fma2(aiz[2*q  ], wiz, cv.x); fma2(aiz[2*q+1], wiz, cv.y);
            fma2(ain[2*q  ], win, cv.x); fma2(ain[2*q+1], win, cv.y);
            fma2(ahr[2*q  ], whr, hv.x); fma2(ahr[2*q+1], whr, hv.y);
            fma2(ahz[2*q  ], whz, hv.x); fma2(ahz[2*q+1], whz, hv.y);
            fma2(ahn[2*q  ], whn, hv.x); fma2(ahn[2*q+1], whn, hv.y);
        }
    }

    const float bir = b_ih[t], biz = b_ih[128 + t], binn = b_ih[256 + t];
    const float bhr = b_hh[t], bhz = b_hh[128 + t], bhn  = b_hh[256 + t];
    #pragma unroll
    for (int p = 0; p < 8; p++){
        #pragma unroll
        for (int hlf = 0; hlf < 2; hlf++){
            int i = 2*p + hlf;
            float ir = hlf ? hi32(air[p]) : lo32(air[p]);
            float iz = hlf ? hi32(aiz[p]) : lo32(aiz[p]);
            float in_= hlf ? hi32(ain[p]) : lo32(ain[p]);
            float hr_= hlf ? hi32(ahr[p]) : lo32(ahr[p]);
            float hz = hlf ? hi32(ahz[p]) : lo32(ahz[p]);
            float hn = hlf ? hi32(ahn[p]) : lo32(ahn[p]);
            float r = sigmoidf_fast(ir + bir + hr_ + bhr);
            float z = sigmoidf_fast(iz + biz + hz + bhz);
            float nn = tanhf_fast(in_ + binn + r * (hn + bhn));
            float h  = h_s[t*20 + i];
            final_out[(size_t)(n0 + i)*128 + t] = (1.0f - z)*nn + z*h;
        }
    }
}

extern "C" void kernel_launch(void* const* d_in, const int* in_sizes, int n_in,
                              void* d_out, int out_size){
    const float* atom = (const float*)d_in[0];
    const float* bond = (const float*)d_in[1];
    const int*   src  = (const int*)  d_in[2];
    // d_in[3] = dst (structurally repeat(arange(N),8); not needed)
    const float* W1  = (const float*)d_in[4];
    const float* b1  = (const float*)d_in[5];
    const float* W2  = (const float*)d_in[6];
    const float* b2  = (const float*)d_in[7];
    const float* Wa  = (const float*)d_in[8];
    const float* ba  = (const float*)d_in[9];
    const float* Ww  = (const float*)d_in[10];
    const float* bw  = (const float*)d_in[11];
    const float* Wih = (const float*)d_in[12];
    const float* bih = (const float*)d_in[13];
    const float* Whh = (const float*)d_in[14];
    const float* bhh = (const float*)d_in[15];
    float* out = (float*)d_out;

    // h1 is the 2nd output; if the harness only sized d_out for `final`,
    // keep h1 in scratch.
    float* h1_out;
    if (out_size >= 2*NNODE*FO){
        h1_out = out + (size_t)NNODE*FO;
    } else {
        void* p = nullptr;
        cudaGetSymbolAddress(&p, g_h1);
        h1_out = (float*)p;
    }

    prep_weights<<<192, 256>>>(W1, Wa, W2, Wih, Whh);
    node_kernel<<<NNODE/32, 128>>>(atom, b1, ba, Ww, h1_out);
    edge_kernel<<<NNODE/16, 128>>>(bond, src, b2, Ww, bw, bih, bhh, h1_out, out);
}

// round 14
// speedup vs baseline: 1.2359x; 1.1910x over previous
#include <cuda_runtime.h>
#include <cuda_bf16.h>

#define NNODE 100000
#define DEG   8
#define FIN   128
#define FB    64
#define FO    128
#define NE    (NNODE*DEG)

typedef unsigned long long u64;

__device__ __forceinline__ u64 pack2(float x){
    u64 r; asm("mov.b64 %0, {%1, %1};" : "=l"(r) : "f"(x)); return r;
}
__device__ __forceinline__ void fma2(u64 &d, u64 a, u64 b){
    asm("fma.rn.f32x2 %0, %1, %2, %0;" : "+l"(d) : "l"(a), "l"(b));
}
__device__ __forceinline__ float lo32(u64 v){ return __uint_as_float((unsigned)v); }
__device__ __forceinline__ float hi32(u64 v){ return __uint_as_float((unsigned)(v >> 32)); }

__device__ __forceinline__ float sigmoidf_fast(float x){
    return __fdividef(1.0f, 1.0f + __expf(-x));
}
__device__ __forceinline__ float tanhf_fast(float x){
    return 1.0f - 2.0f * __fdividef(1.0f, __expf(2.0f * x) + 1.0f);
}

// ---------------- scratch (device globals; no runtime alloc) ----------------
__device__ float g_pre2[NNODE*FO];   // atom @ W2a^T  (no bias)
__device__ float g_nt  [NNODE*FO];   // attend(h1)
__device__ float g_ctx [NNODE*FO];   // elu(attention-weighted sum)
__device__ float g_h1  [NNODE*FO];   // fallback h1 storage
__device__ float g_alpha[NNODE];     // h1 . Ww[:128]
// packed (duplicated f32x2) weights, [k][o] layout
__device__ u64   g_W21P[FIN*FO*2];   // interleaved: [k*128+o]*2 + {0:W2a, 1:W1}
__device__ u64   g_WaP [FO*FO];
__device__ u64   g_W2bP[FB*FO];
// GRU weights, fp32, per (k,t): A = (wir,wiz,win,whr), B = (whz,whn)
__device__ float g_WgA[FO*FO*4];
__device__ float g_WgB[FO*FO*2];

// ---------------- weight prep ----------------
__global__ void prep_weights(const float* __restrict__ W1, const float* __restrict__ Wa,
                             const float* __restrict__ W2,
                             const float* __restrict__ Wih, const float* __restrict__ Whh){
    int idx = blockIdx.x * 256 + threadIdx.x;
    if (idx < 128*128){
        int o = idx >> 7, k = idx & 127;
        g_W21P[(k*128 + o)*2 + 1] = pack2(W1[idx]);
        g_WaP [k*128 + o]         = pack2(Wa[idx]);
    }
    if (idx < 128*192){
        int o = idx / 192, k = idx - o*192;
        float v = W2[idx];
        if (k < 128) g_W21P[(k*128 + o)*2 + 0] = pack2(v);
        else         g_W2bP[(k-128)*128 + o]   = pack2(v);
    }
    if (idx < 384*128){
        int o = idx >> 7, k = idx & 127;
        int t = o & 127, g = o >> 7;
        float vi = Wih[idx], vh = Whh[idx];
        int b4  = (k*128 + t)*4;
        int b2i = (k*128 + t)*2;
        if (g == 0){      g_WgA[b4 + 0] = vi; g_WgA[b4 + 3] = vh; }
        else if (g == 1){ g_WgA[b4 + 1] = vi; g_WgB[b2i + 0] = vh; }
        else {            g_WgA[b4 + 2] = vi; g_WgB[b2i + 1] = vh; }
    }
}

// ---------------- kernel 1: per-node transforms ----------------
// 32 nodes / block, 128 threads. Fused pre2+h1 GEMVs, then nt, alpha.
__global__ void __launch_bounds__(128,4) node_kernel(const float* __restrict__ atom,
                                                     const float* __restrict__ b1,
                                                     const float* __restrict__ ba,
                                                     const float* __restrict__ Ww,
                                                     float* __restrict__ h1_out){
    __shared__ __align__(16) float a_s[128*36];   // [k][node], pitch 36
    __shared__ __align__(16) float h_s[128*36];
    const int t  = threadIdx.x;
    const int n0 = blockIdx.x * 32;

    for (int idx = t; idx < 32*128; idx += 128){
        int i = idx >> 7, k = idx & 127;
        a_s[k*36 + i] = atom[(size_t)(n0 + i)*128 + k];
    }
    __syncthreads();

    // fused: pre2 = atom @ W2a^T   and   h1pre = atom @ W1^T (+b1 folded)
    {
        u64 acc2[16], acc1[16];
        u64 bb1 = pack2(b1[t]);
        #pragma unroll
        for (int p = 0; p < 16; p++){ acc2[p] = 0ull; acc1[p] = bb1; }
        #pragma unroll 2
        for (int k = 0; k < 128; k++){
            const ulonglong2* row = (const ulonglong2*)(a_s + k*36);
            ulonglong2 w = *(const ulonglong2*)(g_W21P + (size_t)(k*128 + t)*2);
            #pragma unroll
            for (int q = 0; q < 8; q++){
                ulonglong2 v = row[q];
                fma2(acc2[2*q  ], w.x, v.x); fma2(acc2[2*q+1], w.x, v.y);
                fma2(acc1[2*q  ], w.y, v.x); fma2(acc1[2*q+1], w.y, v.y);
            }
        }
        #pragma unroll
        for (int p = 0; p < 16; p++){
            g_pre2[(n0 + 2*p    )*128 + t] = lo32(acc2[p]);
            g_pre2[(n0 + 2*p + 1)*128 + t] = hi32(acc2[p]);
        }
        #pragma unroll
        for (int p = 0; p < 16; p++){
            float x0 = lo32(acc1[p]); x0 = x0 > 0.f ? x0 : 0.2f*x0;
            float x1 = hi32(acc1[p]); x1 = x1 > 0.f ? x1 : 0.2f*x1;
            h1_out[(n0 + 2*p    )*128 + t] = x0;
            h1_out[(n0 + 2*p + 1)*128 + t] = x1;
            h_s[t*36 + 2*p    ] = x0;
            h_s[t*36 + 2*p + 1] = x1;
        }
    }
    __syncthreads();

    // nt = h1 @ Wa^T + ba (folded)
    {
        u64 acc[16];
        u64 bba = pack2(ba[t]);
        #pragma unroll
        for (int p = 0; p < 16; p++) acc[p] = bba;
        #pragma unroll 2
        for (int k = 0; k < 128; k++){
            const ulonglong2* row = (const ulonglong2*)(h_s + k*36);
            u64 w = g_WaP[k*128 + t];
            #pragma unroll
            for (int q = 0; q < 8; q++){
                ulonglong2 v = row[q];
                fma2(acc[2*q], w, v.x); fma2(acc[2*q+1], w, v.y);
            }
        }
        #pragma unroll
        for (int p = 0; p < 16; p++){
            g_nt[(n0 + 2*p    )*128 + t] = lo32(acc[p]);
            g_nt[(n0 + 2*p + 1)*128 + t] = hi32(acc[p]);
        }
    }
    // alpha[n] = h1[n] . Ww[:128]
    if (t < 32){
        float s = 0.f;
        #pragma unroll 4
        for (int k = 0; k < 128; k++) s += Ww[k] * h_s[k*36 + t];
        g_alpha[n0 + t] = s;
    }
}

// ---------------- kernel 2a: attention + context ----------------
// 16 nodes = 128 edges / block, 128 threads (thread = feature index).
__global__ void __launch_bounds__(128,4) attn_kernel(const float* __restrict__ bond,
                                                     const int*   __restrict__ src,
                                                     const float* __restrict__ b2,
                                                     const float* __restrict__ Ww,
                                                     const float* __restrict__ bw){
    const int t    = threadIdx.x;
    const int lane = t & 31;
    const int warp = t >> 5;
    const int n0   = blockIdx.x * 16;
    const int e0   = n0 * DEG;

    __shared__ __align__(16) float bond_s[64*36];   // [k][edge-in-chunk], pitch 36
    __shared__ float beta_s[128];
    __shared__ float score_s[128];
    __shared__ float red_s[128];
    __shared__ int   src_s[128];

    src_s[t] = src[e0 + t];
    const float wbt = Ww[128 + t];
    const u64   b2p = pack2(b2[t]);

    // ---- beta per edge, 4 chunks of 32 edges ----
    for (int c = 0; c < 4; c++){
        __syncthreads();
        for (int idx = t; idx < 32*64; idx += 128){
            int j = idx >> 6, k = idx & 63;
            bond_s[k*36 + j] = bond[(size_t)(e0 + c*32 + j)*64 + k];
        }
        __syncthreads();

        u64 acc[16];
        #pragma unroll
        for (int p = 0; p < 16; p++) acc[p] = b2p;
        #pragma unroll 2
        for (int k = 0; k < 64; k++){
            const ulonglong2* row = (const ulonglong2*)(bond_s + k*36);
            u64 w = g_W2bP[k*128 + t];
            #pragma unroll
            for (int q = 0; q < 8; q++){
                ulonglong2 v = row[q];
                fma2(acc[2*q], w, v.x); fma2(acc[2*q+1], w, v.y);
            }
        }

        float vals[32];
        #pragma unroll
        for (int p = 0; p < 16; p++){
            int j0 = 2*p;
            {
                float u = lo32(acc[p]) + g_pre2[(size_t)src_s[c*32 + j0]*128 + t];
                u = u > 0.f ? u : 0.2f*u;
                vals[j0] = wbt * u;
            }
            {
                float u = hi32(acc[p]) + g_pre2[(size_t)src_s[c*32 + j0 + 1]*128 + t];
                u = u > 0.f ? u : 0.2f*u;
                vals[j0 + 1] = wbt * u;
            }
        }
        // log-step transpose-reduce: vals[0] on lane L = sum over lanes of vals[L]
        #pragma unroll
        for (int off = 16; off >= 1; off >>= 1){
            bool up = (lane & off) != 0;
            #pragma unroll
            for (int j = 0; j < off; j++){
                float keep = up ? vals[j + off] : vals[j];
                float send = up ? vals[j]       : vals[j + off];
                vals[j] = keep + __shfl_xor_sync(0xffffffffu, send, off);
            }
        }
        red_s[warp*32 + lane] = vals[0];
        __syncthreads();
        if (t < 32)
            beta_s[c*32 + t] = red_s[t] + red_s[32 + t] + red_s[64 + t] + red_s[96 + t];
    }
    __syncthreads();

    // ---- per-node softmax over 8 edges ----
    if (t < 16){
        float al = g_alpha[n0 + t] + bw[0];
        float lg[8]; float m = -3.0e38f;
        #pragma unroll
        for (int e = 0; e < 8; e++){
            float x = al + beta_s[t*8 + e];
            x = x > 0.f ? x : 0.2f*x;
            lg[e] = x; m = fmaxf(m, x);
        }
        float s = 0.f;
        #pragma unroll
        for (int e = 0; e < 8; e++){ float ex = __expf(lg[e] - m); score_s[t*8 + e] = ex; s += ex; }
        float inv = __fdividef(1.0f, s);
        #pragma unroll
        for (int e = 0; e < 8; e++) score_s[t*8 + e] *= inv;
    }
    __syncthreads();

    // ---- weighted gather of nt, ELU -> g_ctx (coalesced stores) ----
    #pragma unroll
    for (int i = 0; i < 16; i++){
        float a = 0.f;
        #pragma unroll
        for (int e = 0; e < 8; e++)
            a += score_s[i*8 + e] * g_nt[(size_t)src_s[i*8 + e]*128 + t];
        g_ctx[(size_t)(n0 + i)*128 + t] = a > 0.f ? a : (__expf(a) - 1.0f);
    }
}

// ---------------- kernel 2b: GRU ----------------
// 16 nodes / block, 128 threads. 4 merged accumulator sets (r,z,in,hn).
__global__ void __launch_bounds__(128,4) gru_kernel(const float* __restrict__ b_ih,
                                                    const float* __restrict__ b_hh,
                                                    const float* __restrict__ h1_in,
                                                    float* __restrict__ final_out){
    const int t  = threadIdx.x;
    const int n0 = blockIdx.x * 16;

    __shared__ __align__(16) float ctx_s[128*20];   // [k][node], pitch 20
    __shared__ __align__(16) float h_s  [128*20];

    #pragma unroll
    for (int i = 0; i < 16; i++){
        ctx_s[t*20 + i] = g_ctx[(size_t)(n0 + i)*128 + t];
        h_s  [t*20 + i] = h1_in[(size_t)(n0 + i)*128 + t];
    }
    __syncthreads();

    // merged accumulators: r = i_r + h_r (+biases), z likewise; n-input; n-hidden
    u64 ar[8], az[8], an_[8], ahn[8];
    {
        u64 br = pack2(b_ih[t]       + b_hh[t]);
        u64 bz = pack2(b_ih[128 + t] + b_hh[128 + t]);
        u64 bn = pack2(b_ih[256 + t]);
        u64 bh = pack2(b_hh[256 + t]);
        #pragma unroll
        for (int p = 0; p < 8; p++){ ar[p] = br; az[p] = bz; an_[p] = bn; ahn[p] = bh; }
    }

    #pragma unroll 2
    for (int k = 0; k < 128; k++){
        float4 A = *(const float4*)(g_WgA + (size_t)(k*128 + t)*4);  // ir, iz, in, hr
        float2 B = *(const float2*)(g_WgB + (size_t)(k*128 + t)*2);  // hz, hn
        u64 wir = pack2(A.x), wiz = pack2(A.y), win = pack2(A.z);
        u64 whr = pack2(A.w), whz = pack2(B.x), whn = pack2(B.y);
        const ulonglong2* cr = (const ulonglong2*)(ctx_s + k*20);
        const ulonglong2* hh = (const ulonglong2*)(h_s   + k*20);
        #pragma unroll
        for (int q = 0; q < 4; q++){
            ulonglong2 cv = cr[q];
            ulonglong2 hv = hh[q];
            fma2(ar [2*q  ], wir, cv.x); fma2(ar [2*q  ], whr, hv.x);
            fma2(ar [2*q+1], wir, cv.y); fma2(ar [2*q+1], whr, hv.y);
            fma2(az [2*q  ], wiz, cv.x); fma2(az [2*q  ], whz, hv.x);
            fma2(az [2*q+1], wiz, cv.y); fma2(az [2*q+1], whz, hv.y);
            fma2(an_[2*q  ], win, cv.x); fma2(an_[2*q+1], win, cv.y);
            fma2(ahn[2*q  ], whn, hv.x); fma2(ahn[2*q+1], whn, hv.y);
        }
    }

    #pragma unroll
    for (int p = 0; p < 8; p++){
        #pragma unroll
        for (int hlf = 0; hlf < 2; hlf++){
            int i = 2*p + hlf;
            float rv = hlf ? hi32(ar [p]) : lo32(ar [p]);
            float zv = hlf ? hi32(az [p]) : lo32(az [p]);
            float nv = hlf ? hi32(an_[p]) : lo32(an_[p]);
            float hv = hlf ? hi32(ahn[p]) : lo32(ahn[p]);
            float r = sigmoidf_fast(rv);
            float z = sigmoidf_fast(zv);
            float nn = tanhf_fast(nv + r * hv);
            float h  = h_s[t*20 + i];
            final_out[(size_t)(n0 + i)*128 + t] = (1.0f - z)*nn + z*h;
        }
    }
}

extern "C" void kernel_launch(void* const* d_in, const int* in_sizes, int n_in,
                              void* d_out, int out_size){
    const float* atom = (const float*)d_in[0];
    const float* bond = (const float*)d_in[1];
    const int*   src  = (const int*)  d_in[2];
    // d_in[3] = dst (structurally repeat(arange(N),8); not needed)
    const float* W1  = (const float*)d_in[4];
    const float* b1  = (const float*)d_in[5];
    const float* W2  = (const float*)d_in[6];
    const float* b2  = (const float*)d_in[7];
    const float* Wa  = (const float*)d_in[8];
    const float* ba  = (const float*)d_in[9];
    const float* Ww  = (const float*)d_in[10];
    const float* bw  = (const float*)d_in[11];
    const float* Wih = (const float*)d_in[12];
    const float* bih = (const float*)d_in[13];
    const float* Whh = (const float*)d_in[14];
    const float* bhh = (const float*)d_in[15];
    float* out = (float*)d_out;

    // h1 is the 2nd output; if the harness only sized d_out for `final`,
    // keep h1 in scratch.
    float* h1_out;
    if (out_size >= 2*NNODE*FO){
        h1_out = out + (size_t)NNODE*FO;
    } else {
        void* p = nullptr;
        cudaGetSymbolAddress(&p, g_h1);
        h1_out = (float*)p;
    }

    prep_weights<<<192, 256>>>(W1, Wa, W2, Wih, Whh);
    node_kernel<<<NNODE/32, 128>>>(atom, b1, ba, Ww, h1_out);
    attn_kernel<<<NNODE/16, 128>>>(bond, src, b2, Ww, bw);
    gru_kernel <<<NNODE/16, 128>>>(bih, bhh, h1_out, out);
}

// round 15
// speedup vs baseline: 1.2428x; 1.0056x over previous
#include <cuda_runtime.h>
#include <cuda_bf16.h>

#define NNODE 100000
#define DEG   8
#define FIN   128
#define FB    64
#define FO    128
#define NE    (NNODE*DEG)

typedef unsigned long long u64;

__device__ __forceinline__ u64 pack2(float x){
    u64 r; asm("mov.b64 %0, {%1, %1};" : "=l"(r) : "f"(x)); return r;
}
__device__ __forceinline__ void fma2(u64 &d, u64 a, u64 b){
    asm("fma.rn.f32x2 %0, %1, %2, %0;" : "+l"(d) : "l"(a), "l"(b));
}
__device__ __forceinline__ float lo32(u64 v){ return __uint_as_float((unsigned)v); }
__device__ __forceinline__ float hi32(u64 v){ return __uint_as_float((unsigned)(v >> 32)); }

__device__ __forceinline__ float sigmoidf_fast(float x){
    return __fdividef(1.0f, 1.0f + __expf(-x));
}
__device__ __forceinline__ float tanhf_fast(float x){
    return 1.0f - 2.0f * __fdividef(1.0f, __expf(2.0f * x) + 1.0f);
}

// ---------------- scratch (device globals; no runtime alloc) ----------------
__device__ float g_pre2[NNODE*FO];   // atom @ W2a^T  (no bias)
__device__ float g_nt  [NNODE*FO];   // attend(h1)
__device__ float g_ctx [NNODE*FO];   // elu(attention-weighted sum)
__device__ float g_h1  [NNODE*FO];   // fallback h1 storage
__device__ float g_alpha[NNODE];     // h1 . Ww[:128]
// packed (duplicated f32x2) weights, [k][o] layout
__device__ u64   g_W21P[FIN*FO*2];   // interleaved: [k*128+o]*2 + {0:W2a, 1:W1}
__device__ u64   g_WaP [FO*FO];
__device__ u64   g_W2bP[FB*FO];
// GRU weights, fp32, per (k,t): A = (wir,wiz,win,whr), B = (whz,whn)
__device__ float g_WgA[FO*FO*4];
__device__ float g_WgB[FO*FO*2];

// ---------------- weight prep ----------------
__global__ void prep_weights(const float* __restrict__ W1, const float* __restrict__ Wa,
                             const float* __restrict__ W2,
                             const float* __restrict__ Wih, const float* __restrict__ Whh){
    int idx = blockIdx.x * 256 + threadIdx.x;
    if (idx < 128*128){
        int o = idx >> 7, k = idx & 127;
        g_W21P[(k*128 + o)*2 + 1] = pack2(W1[idx]);
        g_WaP [k*128 + o]         = pack2(Wa[idx]);
    }
    if (idx < 128*192){
        int o = idx / 192, k = idx - o*192;
        float v = W2[idx];
        if (k < 128) g_W21P[(k*128 + o)*2 + 0] = pack2(v);
        else         g_W2bP[(k-128)*128 + o]   = pack2(v);
    }
    if (idx < 384*128){
        int o = idx >> 7, k = idx & 127;
        int t = o & 127, g = o >> 7;
        float vi = Wih[idx], vh = Whh[idx];
        int b4  = (k*128 + t)*4;
        int b2i = (k*128 + t)*2;
        if (g == 0){      g_WgA[b4 + 0] = vi; g_WgA[b4 + 3] = vh; }
        else if (g == 1){ g_WgA[b4 + 1] = vi; g_WgB[b2i + 0] = vh; }
        else {            g_WgA[b4 + 2] = vi; g_WgB[b2i + 1] = vh; }
    }
}

// ---------------- kernel 1: per-node transforms ----------------
// 32 nodes / block, 128 threads. Fused pre2+h1 GEMVs, then nt, alpha.
__global__ void __launch_bounds__(128,4) node_kernel(const float* __restrict__ atom,
                                                     const float* __restrict__ b1,
                                                     const float* __restrict__ ba,
                                                     const float* __restrict__ Ww,
                                                     float* __restrict__ h1_out){
    __shared__ __align__(16) float a_s[128*36];   // [k][node], pitch 36
    __shared__ __align__(16) float h_s[128*36];
    const int t  = threadIdx.x;
    const int n0 = blockIdx.x * 32;

    for (int idx = t; idx < 32*128; idx += 128){
        int i = idx >> 7, k = idx & 127;
        a_s[k*36 + i] = atom[(size_t)(n0 + i)*128 + k];
    }
    __syncthreads();

    // fused: pre2 = atom @ W2a^T   and   h1pre = atom @ W1^T (+b1 folded)
    {
        u64 acc2[16], acc1[16];
        u64 bb1 = pack2(b1[t]);
        #pragma unroll
        for (int p = 0; p < 16; p++){ acc2[p] = 0ull; acc1[p] = bb1; }
        #pragma unroll 2
        for (int k = 0; k < 128; k++){
            const ulonglong2* row = (const ulonglong2*)(a_s + k*36);
            ulonglong2 w = *(const ulonglong2*)(g_W21P + (size_t)(k*128 + t)*2);
            #pragma unroll
            for (int q = 0; q < 8; q++){
                ulonglong2 v = row[q];
                fma2(acc2[2*q  ], w.x, v.x); fma2(acc2[2*q+1], w.x, v.y);
                fma2(acc1[2*q  ], w.y, v.x); fma2(acc1[2*q+1], w.y, v.y);
            }
        }
        #pragma unroll
        for (int p = 0; p < 16; p++){
            g_pre2[(n0 + 2*p    )*128 + t] = lo32(acc2[p]);
            g_pre2[(n0 + 2*p + 1)*128 + t] = hi32(acc2[p]);
        }
        #pragma unroll
        for (int p = 0; p < 16; p++){
            float x0 = lo32(acc1[p]); x0 = x0 > 0.f ? x0 : 0.2f*x0;
            float x1 = hi32(acc1[p]); x1 = x1 > 0.f ? x1 : 0.2f*x1;
            h1_out[(n0 + 2*p    )*128 + t] = x0;
            h1_out[(n0 + 2*p + 1)*128 + t] = x1;
            h_s[t*36 + 2*p    ] = x0;
            h_s[t*36 + 2*p + 1] = x1;
        }
    }
    __syncthreads();

    // nt = h1 @ Wa^T + ba (folded)
    {
        u64 acc[16];
        u64 bba = pack2(ba[t]);
        #pragma unroll
        for (int p = 0; p < 16; p++) acc[p] = bba;
        #pragma unroll 2
        for (int k = 0; k < 128; k++){
            const ulonglong2* row = (const ulonglong2*)(h_s + k*36);
            u64 w = g_WaP[k*128 + t];
            #pragma unroll
            for (int q = 0; q < 8; q++){
                ulonglong2 v = row[q];
                fma2(acc[2*q], w, v.x); fma2(acc[2*q+1], w, v.y);
            }
        }
        #pragma unroll
        for (int p = 0; p < 16; p++){
            g_nt[(n0 + 2*p    )*128 + t] = lo32(acc[p]);
            g_nt[(n0 + 2*p + 1)*128 + t] = hi32(acc[p]);
        }
    }
    // alpha[n] = h1[n] . Ww[:128]
    if (t < 32){
        float s = 0.f;
        #pragma unroll 4
        for (int k = 0; k < 128; k++) s += Ww[k] * h_s[k*36 + t];
        g_alpha[n0 + t] = s;
    }
}

// ---------------- kernel 2a: attention + context ----------------
// 16 nodes = 128 edges / block, 128 threads (thread = feature index).
__global__ void __launch_bounds__(128,4) attn_kernel(const float* __restrict__ bond,
                                                     const int*   __restrict__ src,
                                                     const float* __restrict__ b2,
                                                     const float* __restrict__ Ww,
                                                     const float* __restrict__ bw){
    const int t    = threadIdx.x;
    const int lane = t & 31;
    const int warp = t >> 5;
    const int n0   = blockIdx.x * 16;
    const int e0   = n0 * DEG;

    __shared__ __align__(16) float bond_s[64*36];   // [k][edge-in-chunk], pitch 36
    __shared__ float beta_s[128];
    __shared__ float score_s[128];
    __shared__ float red_s[128];
    __shared__ int   src_s[128];

    src_s[t] = src[e0 + t];
    const float wbt = Ww[128 + t];
    const u64   b2p = pack2(b2[t]);

    // ---- beta per edge, 4 chunks of 32 edges ----
    for (int c = 0; c < 4; c++){
        __syncthreads();
        for (int idx = t; idx < 32*64; idx += 128){
            int j = idx >> 6, k = idx & 63;
            bond_s[k*36 + j] = bond[(size_t)(e0 + c*32 + j)*64 + k];
        }
        __syncthreads();

        u64 acc[16];
        #pragma unroll
        for (int p = 0; p < 16; p++) acc[p] = b2p;
        #pragma unroll 2
        for (int k = 0; k < 64; k++){
            const ulonglong2* row = (const ulonglong2*)(bond_s + k*36);
            u64 w = g_W2bP[k*128 + t];
            #pragma unroll
            for (int q = 0; q < 8; q++){
                ulonglong2 v = row[q];
                fma2(acc[2*q], w, v.x); fma2(acc[2*q+1], w, v.y);
            }
        }

        float vals[32];
        #pragma unroll
        for (int p = 0; p < 16; p++){
            int j0 = 2*p;
            {
                float u = lo32(acc[p]) + g_pre2[(size_t)src_s[c*32 + j0]*128 + t];
                u = u > 0.f ? u : 0.2f*u;
                vals[j0] = wbt * u;
            }
            {
                float u = hi32(acc[p]) + g_pre2[(size_t)src_s[c*32 + j0 + 1]*128 + t];
                u = u > 0.f ? u : 0.2f*u;
                vals[j0 + 1] = wbt * u;
            }
        }
        // log-step transpose-reduce: vals[0] on lane L = sum over lanes of vals[L]
        #pragma unroll
        for (int off = 16; off >= 1; off >>= 1){
            bool up = (lane & off) != 0;
            #pragma unroll
            for (int j = 0; j < off; j++){
                float keep = up ? vals[j + off] : vals[j];
                float send = up ? vals[j]       : vals[j + off];
                vals[j] = keep + __shfl_xor_sync(0xffffffffu, send, off);
            }
        }
        red_s[warp*32 + lane] = vals[0];
        __syncthreads();
        if (t < 32)
            beta_s[c*32 + t] = red_s[t] + red_s[32 + t] + red_s[64 + t] + red_s[96 + t];
    }
    __syncthreads();

    // ---- per-node softmax over 8 edges ----
    if (t < 16){
        float al = g_alpha[n0 + t] + bw[0];
        float lg[8]; float m = -3.0e38f;
        #pragma unroll
        for (int e = 0; e < 8; e++){
            float x = al + beta_s[t*8 + e];
            x = x > 0.f ? x : 0.2f*x;
            lg[e] = x; m = fmaxf(m, x);
        }
        float s = 0.f;
        #pragma unroll
        for (int e = 0; e < 8; e++){ float ex = __expf(lg[e] - m); score_s[t*8 + e] = ex; s += ex; }
        float inv = __fdividef(1.0f, s);
        #pragma unroll
        for (int e = 0; e < 8; e++) score_s[t*8 + e] *= inv;
    }
    __syncthreads();

    // ---- weighted gather of nt, ELU -> g_ctx (coalesced stores) ----
    #pragma unroll
    for (int i = 0; i < 16; i++){
        float a = 0.f;
        #pragma unroll
        for (int e = 0; e < 8; e++)
            a += score_s[i*8 + e] * g_nt[(size_t)src_s[i*8 + e]*128 + t];
        g_ctx[(size_t)(n0 + i)*128 + t] = a > 0.f ? a : (__expf(a) - 1.0f);
    }
}

// ---------------- kernel 2b: GRU ----------------
// 16 nodes / block, 128 threads. 4 merged accumulator sets (r,z,in,hn).
__global__ void __launch_bounds__(128,4) gru_kernel(const float* __restrict__ b_ih,
                                                    const float* __restrict__ b_hh,
                                                    const float* __restrict__ h1_in,
                                                    float* __restrict__ final_out){
    const int t  = threadIdx.x;
    const int n0 = blockIdx.x * 16;

    __shared__ __align__(16) float ctx_s[128*20];   // [k][node], pitch 20
    __shared__ __align__(16) float h_s  [128*20];

    #pragma unroll
    for (int i = 0; i < 16; i++){
        ctx_s[t*20 + i] = g_ctx[(size_t)(n0 + i)*128 + t];
        h_s  [t*20 + i] = h1_in[(size_t)(n0 + i)*128 + t];
    }
    __syncthreads();

    // merged accumulators: r = i_r + h_r (+biases), z likewise; n-input; n-hidden
    u64 ar[8], az[8], an_[8], ahn[8];
    {
        u64 br = pack2(b_ih[t]       + b_hh[t]);
        u64 bz = pack2(b_ih[128 + t] + b_hh[128 + t]);
        u64 bn = pack2(b_ih[256 + t]);
        u64 bh = pack2(b_hh[256 + t]);
        #pragma unroll
        for (int p = 0; p < 8; p++){ ar[p] = br; az[p] = bz; an_[p] = bn; ahn[p] = bh; }
    }

    #pragma unroll 2
    for (int k = 0; k < 128; k++){
        float4 A = *(const float4*)(g_WgA + (size_t)(k*128 + t)*4);  // ir, iz, in, hr
        float2 B = *(const float2*)(g_WgB + (size_t)(k*128 + t)*2);  // hz, hn
        u64 wir = pack2(A.x), wiz = pack2(A.y), win = pack2(A.z);
        u64 whr = pack2(A.w), whz = pack2(B.x), whn = pack2(B.y);
        const ulonglong2* cr = (const ulonglong2*)(ctx_s + k*20);
        const ulonglong2* hh = (const ulonglong2*)(h_s   + k*20);
        #pragma unroll
        for (int q = 0; q < 4; q++){
            ulonglong2 cv = cr[q];
            ulonglong2 hv = hh[q];
            fma2(ar [2*q  ], wir, cv.x); fma2(ar [2*q  ], whr, hv.x);
            fma2(ar [2*q+1], wir, cv.y); fma2(ar [2*q+1], whr, hv.y);
            fma2(az [2*q  ], wiz, cv.x); fma2(az [2*q  ], whz, hv.x);
            fma2(az [2*q+1], wiz, cv.y); fma2(az [2*q+1], whz, hv.y);
            fma2(an_[2*q  ], win, cv.x); fma2(an_[2*q+1], win, cv.y);
            fma2(ahn[2*q  ], whn, hv.x); fma2(ahn[2*q+1], whn, hv.y);
        }
    }

    #pragma unroll
    for (int p = 0; p < 8; p++){
        #pragma unroll
        for (int hlf = 0; hlf < 2; hlf++){
            int i = 2*p + hlf;
            float rv = hlf ? hi32(ar [p]) : lo32(ar [p]);
            float zv = hlf ? hi32(az [p]) : lo32(az [p]);
            float nv = hlf ? hi32(an_[p]) : lo32(an_[p]);
            float hv = hlf ? hi32(ahn[p]) : lo32(ahn[p]);
            float r = sigmoidf_fast(rv);
            float z = sigmoidf_fast(zv);
            float nn = tanhf_fast(nv + r * hv);
            float h  = h_s[t*20 + i];
            final_out[(size_t)(n0 + i)*128 + t] = (1.0f - z)*nn + z*h;
        }
    }
}

extern "C" void kernel_launch(void* const* d_in, const int* in_sizes, int n_in,
                              void* d_out, int out_size){
    const float* atom = (const float*)d_in[0];
    const float* bond = (const float*)d_in[1];
    const int*   src  = (const int*)  d_in[2];
    // d_in[3] = dst (structurally repeat(arange(N),8); not needed)
    const float* W1  = (const float*)d_in[4];
    const float* b1  = (const float*)d_in[5];
    const float* W2  = (const float*)d_in[6];
    const float* b2  = (const float*)d_in[7];
    const float* Wa  = (const float*)d_in[8];
    const float* ba  = (const float*)d_in[9];
    const float* Ww  = (const float*)d_in[10];
    const float* bw  = (const float*)d_in[11];
    const float* Wih = (const float*)d_in[12];
    const float* bih = (const float*)d_in[13];
    const float* Whh = (const float*)d_in[14];
    const float* bhh = (const float*)d_in[15];
    float* out = (float*)d_out;

    // h1 is the 2nd output; if the harness only sized d_out for `final`,
    // keep h1 in scratch.
    float* h1_out;
    if (out_size >= 2*NNODE*FO){
        h1_out = out + (size_t)NNODE*FO;
    } else {
        void* p = nullptr;
        cudaGetSymbolAddress(&p, g_h1);
        h1_out = (float*)p;
    }

    prep_weights<<<192, 256>>>(W1, Wa, W2, Wih, Whh);
    node_kernel<<<NNODE/32, 128>>>(atom, b1, ba, Ww, h1_out);
    attn_kernel<<<NNODE/16, 128>>>(bond, src, b2, Ww, bw);
    gru_kernel <<<NNODE/16, 128>>>(bih, bhh, h1_out, out);
}

// round 16
// speedup vs baseline: 1.2448x; 1.0016x over previous
#include <cuda_runtime.h>
#include <cuda_bf16.h>

#define NNODE 100000
#define DEG   8
#define FIN   128
#define FB    64
#define FO    128
#define NE    (NNODE*DEG)

typedef unsigned long long u64;

__device__ __forceinline__ u64 pack2(float x){
    u64 r; asm("mov.b64 %0, {%1, %1};" : "=l"(r) : "f"(x)); return r;
}
__device__ __forceinline__ void fma2(u64 &d, u64 a, u64 b){
    asm("fma.rn.f32x2 %0, %1, %2, %0;" : "+l"(d) : "l"(a), "l"(b));
}
__device__ __forceinline__ float lo32(u64 v){ return __uint_as_float((unsigned)v); }
__device__ __forceinline__ float hi32(u64 v){ return __uint_as_float((unsigned)(v >> 32)); }

__device__ __forceinline__ float sigmoidf_fast(float x){
    return __fdividef(1.0f, 1.0f + __expf(-x));
}
__device__ __forceinline__ float tanhf_fast(float x){
    return 1.0f - 2.0f * __fdividef(1.0f, __expf(2.0f * x) + 1.0f);
}

// ---------------- scratch (device globals; no runtime alloc) ----------------
__device__ float g_pre2[NNODE*FO];   // atom @ W2a^T  (no bias)
__device__ float g_nt  [NNODE*FO];   // attend(h1)
__device__ float g_ctx [NNODE*FO];   // elu(attention-weighted sum)
__device__ float g_h1  [NNODE*FO];   // fallback h1 storage
__device__ float g_alpha[NNODE];     // h1 . Ww[:128]
// packed (duplicated f32x2) weights, [k][o] layout
__device__ u64   g_W21P[FIN*FO*2];   // interleaved: [k*128+o]*2 + {0:W2a, 1:W1}
__device__ u64   g_WaP [FO*FO];
__device__ u64   g_W2bP[FB*FO];
// GRU weights, fp32, per (k,t): A = (wir,wiz,win,whr), B = (whz,whn)
__device__ float g_WgA[FO*FO*4];
__device__ float g_WgB[FO*FO*2];

// ---------------- weight prep ----------------
__global__ void prep_weights(const float* __restrict__ W1, const float* __restrict__ Wa,
                             const float* __restrict__ W2,
                             const float* __restrict__ Wih, const float* __restrict__ Whh){
    int idx = blockIdx.x * 256 + threadIdx.x;
    if (idx < 128*128){
        int o = idx >> 7, k = idx & 127;
        g_W21P[(k*128 + o)*2 + 1] = pack2(W1[idx]);
        g_WaP [k*128 + o]         = pack2(Wa[idx]);
    }
    if (idx < 128*192){
        int o = idx / 192, k = idx - o*192;
        float v = W2[idx];
        if (k < 128) g_W21P[(k*128 + o)*2 + 0] = pack2(v);
        else         g_W2bP[(k-128)*128 + o]   = pack2(v);
    }
    if (idx < 384*128){
        int o = idx >> 7, k = idx & 127;
        int t = o & 127, g = o >> 7;
        float vi = Wih[idx], vh = Whh[idx];
        int b4  = (k*128 + t)*4;
        int b2i = (k*128 + t)*2;
        if (g == 0){      g_WgA[b4 + 0] = vi; g_WgA[b4 + 3] = vh; }
        else if (g == 1){ g_WgA[b4 + 1] = vi; g_WgB[b2i + 0] = vh; }
        else {            g_WgA[b4 + 2] = vi; g_WgB[b2i + 1] = vh; }
    }
}

// ---------------- kernel 1: per-node transforms ----------------
// 32 nodes / block, 128 threads. Fused pre2+h1 GEMVs, then nt, alpha.
__global__ void __launch_bounds__(128,4) node_kernel(const float* __restrict__ atom,
                                                     const float* __restrict__ b1,
                                                     const float* __restrict__ ba,
                                                     const float* __restrict__ Ww,
                                                     float* __restrict__ h1_out){
    __shared__ __align__(16) float a_s[128*36];   // [k][node], pitch 36
    __shared__ __align__(16) float h_s[128*36];
    const int t  = threadIdx.x;
    const int n0 = blockIdx.x * 32;

    for (int idx = t; idx < 32*128; idx += 128){
        int i = idx >> 7, k = idx & 127;
        a_s[k*36 + i] = atom[(size_t)(n0 + i)*128 + k];
    }
    __syncthreads();

    // fused: pre2 = atom @ W2a^T   and   h1pre = atom @ W1^T (+b1 folded)
    {
        u64 acc2[16], acc1[16];
        u64 bb1 = pack2(b1[t]);
        #pragma unroll
        for (int p = 0; p < 16; p++){ acc2[p] = 0ull; acc1[p] = bb1; }
        #pragma unroll 2
        for (int k = 0; k < 128; k++){
            const ulonglong2* row = (const ulonglong2*)(a_s + k*36);
            ulonglong2 w = *(const ulonglong2*)(g_W21P + (size_t)(k*128 + t)*2);
            #pragma unroll
            for (int q = 0; q < 8; q++){
                ulonglong2 v = row[q];
                fma2(acc2[2*q  ], w.x, v.x); fma2(acc2[2*q+1], w.x, v.y);
                fma2(acc1[2*q  ], w.y, v.x); fma2(acc1[2*q+1], w.y, v.y);
            }
        }
        #pragma unroll
        for (int p = 0; p < 16; p++){
            g_pre2[(n0 + 2*p    )*128 + t] = lo32(acc2[p]);
            g_pre2[(n0 + 2*p + 1)*128 + t] = hi32(acc2[p]);
        }
        #pragma unroll
        for (int p = 0; p < 16; p++){
            float x0 = lo32(acc1[p]); x0 = x0 > 0.f ? x0 : 0.2f*x0;
            float x1 = hi32(acc1[p]); x1 = x1 > 0.f ? x1 : 0.2f*x1;
            h1_out[(n0 + 2*p    )*128 + t] = x0;
            h1_out[(n0 + 2*p + 1)*128 + t] = x1;
            h_s[t*36 + 2*p    ] = x0;
            h_s[t*36 + 2*p + 1] = x1;
        }
    }
    __syncthreads();

    // nt = h1 @ Wa^T + ba (folded)
    {
        u64 acc[16];
        u64 bba = pack2(ba[t]);
        #pragma unroll
        for (int p = 0; p < 16; p++) acc[p] = bba;
        #pragma unroll 2
        for (int k = 0; k < 128; k++){
            const ulonglong2* row = (const ulonglong2*)(h_s + k*36);
            u64 w = g_WaP[k*128 + t];
            #pragma unroll
            for (int q = 0; q < 8; q++){
                ulonglong2 v = row[q];
                fma2(acc[2*q], w, v.x); fma2(acc[2*q+1], w, v.y);
            }
        }
        #pragma unroll
        for (int p = 0; p < 16; p++){
            g_nt[(n0 + 2*p    )*128 + t] = lo32(acc[p]);
            g_nt[(n0 + 2*p + 1)*128 + t] = hi32(acc[p]);
        }
    }
    // alpha[n] = h1[n] . Ww[:128]
    if (t < 32){
        float s = 0.f;
        #pragma unroll 4
        for (int k = 0; k < 128; k++) s += Ww[k] * h_s[k*36 + t];
        g_alpha[n0 + t] = s;
    }
}

// ---------------- kernel 2a: attention + context ----------------
// 16 nodes = 128 edges / block, 128 threads (thread = feature index).
__global__ void __launch_bounds__(128,4) attn_kernel(const float* __restrict__ bond,
                                                     const int*   __restrict__ src,
                                                     const float* __restrict__ b2,
                                                     const float* __restrict__ Ww,
                                                     const float* __restrict__ bw){
    const int t    = threadIdx.x;
    const int lane = t & 31;
    const int warp = t >> 5;
    const int n0   = blockIdx.x * 16;
    const int e0   = n0 * DEG;

    __shared__ __align__(16) float bond_s[64*36];   // [k][edge-in-chunk], pitch 36
    __shared__ float beta_s[128];
    __shared__ float score_s[128];
    __shared__ float red_s[128];
    __shared__ int   src_s[128];

    src_s[t] = src[e0 + t];
    const float wbt = Ww[128 + t];
    const u64   b2p = pack2(b2[t]);

    // ---- beta per edge, 4 chunks of 32 edges ----
    for (int c = 0; c < 4; c++){
        __syncthreads();
        for (int idx = t; idx < 32*64; idx += 128){
            int j = idx >> 6, k = idx & 63;
            bond_s[k*36 + j] = bond[(size_t)(e0 + c*32 + j)*64 + k];
        }
        __syncthreads();

        u64 acc[16];
        #pragma unroll
        for (int p = 0; p < 16; p++) acc[p] = b2p;
        #pragma unroll 2
        for (int k = 0; k < 64; k++){
            const ulonglong2* row = (const ulonglong2*)(bond_s + k*36);
            u64 w = g_W2bP[k*128 + t];
            #pragma unroll
            for (int q = 0; q < 8; q++){
                ulonglong2 v = row[q];
                fma2(acc[2*q], w, v.x); fma2(acc[2*q+1], w, v.y);
            }
        }

        float vals[32];
        #pragma unroll
        for (int p = 0; p < 16; p++){
            int j0 = 2*p;
            {
                float u = lo32(acc[p]) + g_pre2[(size_t)src_s[c*32 + j0]*128 + t];
                u = u > 0.f ? u : 0.2f*u;
                vals[j0] = wbt * u;
            }
            {
                float u = hi32(acc[p]) + g_pre2[(size_t)src_s[c*32 + j0 + 1]*128 + t];
                u = u > 0.f ? u : 0.2f*u;
                vals[j0 + 1] = wbt * u;
            }
        }
        // log-step transpose-reduce: vals[0] on lane L = sum over lanes of vals[L]
        #pragma unroll
        for (int off = 16; off >= 1; off >>= 1){
            bool up = (lane & off) != 0;
            #pragma unroll
            for (int j = 0; j < off; j++){
                float keep = up ? vals[j + off] : vals[j];
                float send = up ? vals[j]       : vals[j + off];
                vals[j] = keep + __shfl_xor_sync(0xffffffffu, send, off);
            }
        }
        red_s[warp*32 + lane] = vals[0];
        __syncthreads();
        if (t < 32)
            beta_s[c*32 + t] = red_s[t] + red_s[32 + t] + red_s[64 + t] + red_s[96 + t];
    }
    __syncthreads();

    // ---- per-node softmax over 8 edges ----
    if (t < 16){
        float al = g_alpha[n0 + t] + bw[0];
        float lg[8]; float m = -3.0e38f;
        #pragma unroll
        for (int e = 0; e < 8; e++){
            float x = al + beta_s[t*8 + e];
            x = x > 0.f ? x : 0.2f*x;
            lg[e] = x; m = fmaxf(m, x);
        }
        float s = 0.f;
        #pragma unroll
        for (int e = 0; e < 8; e++){ float ex = __expf(lg[e] - m); score_s[t*8 + e] = ex; s += ex; }
        float inv = __fdividef(1.0f, s);
        #pragma unroll
        for (int e = 0; e < 8; e++) score_s[t*8 + e] *= inv;
    }
    __syncthreads();

    // ---- weighted gather of nt, ELU -> g_ctx (coalesced stores) ----
    #pragma unroll
    for (int i = 0; i < 16; i++){
        float a = 0.f;
        #pragma unroll
        for (int e = 0; e < 8; e++)
            a += score_s[i*8 + e] * g_nt[(size_t)src_s[i*8 + e]*128 + t];
        g_ctx[(size_t)(n0 + i)*128 + t] = a > 0.f ? a : (__expf(a) - 1.0f);
    }
}

// ---------------- kernel 2b: GRU ----------------
// 16 nodes / block, 128 threads. 4 merged accumulator sets (r,z,in,hn).
__global__ void __launch_bounds__(128,4) gru_kernel(const float* __restrict__ b_ih,
                                                    const float* __restrict__ b_hh,
                                                    const float* __restrict__ h1_in,
                                                    float* __restrict__ final_out){
    const int t  = threadIdx.x;
    const int n0 = blockIdx.x * 16;

    __shared__ __align__(16) float ctx_s[128*20];   // [k][node], pitch 20
    __shared__ __align__(16) float h_s  [128*20];

    #pragma unroll
    for (int i = 0; i < 16; i++){
        ctx_s[t*20 + i] = g_ctx[(size_t)(n0 + i)*128 + t];
        h_s  [t*20 + i] = h1_in[(size_t)(n0 + i)*128 + t];
    }
    __syncthreads();

    // merged accumulators: r = i_r + h_r (+biases), z likewise; n-input; n-hidden
    u64 ar[8], az[8], an_[8], ahn[8];
    {
        u64 br = pack2(b_ih[t]       + b_hh[t]);
        u64 bz = pack2(b_ih[128 + t] + b_hh[128 + t]);
        u64 bn = pack2(b_ih[256 + t]);
        u64 bh = pack2(b_hh[256 + t]);
        #pragma unroll
        for (int p = 0; p < 8; p++){ ar[p] = br; az[p] = bz; an_[p] = bn; ahn[p] = bh; }
    }

    #pragma unroll 2
    for (int k = 0; k < 128; k++){
        float4 A = *(const float4*)(g_WgA + (size_t)(k*128 + t)*4);  // ir, iz, in, hr
        float2 B = *(const float2*)(g_WgB + (size_t)(k*128 + t)*2);  // hz, hn
        u64 wir = pack2(A.x), wiz = pack2(A.y), win = pack2(A.z);
        u64 whr = pack2(A.w), whz = pack2(B.x), whn = pack2(B.y);
        const ulonglong2* cr = (const ulonglong2*)(ctx_s + k*20);
        const ulonglong2* hh = (const ulonglong2*)(h_s   + k*20);
        #pragma unroll
        for (int q = 0; q < 4; q++){
            ulonglong2 cv = cr[q];
            ulonglong2 hv = hh[q];
            fma2(ar [2*q  ], wir, cv.x); fma2(ar [2*q  ], whr, hv.x);
            fma2(ar [2*q+1], wir, cv.y); fma2(ar [2*q+1], whr, hv.y);
            fma2(az [2*q  ], wiz, cv.x); fma2(az [2*q  ], whz, hv.x);
            fma2(az [2*q+1], wiz, cv.y); fma2(az [2*q+1], whz, hv.y);
            fma2(an_[2*q  ], win, cv.x); fma2(an_[2*q+1], win, cv.y);
            fma2(ahn[2*q  ], whn, hv.x); fma2(ahn[2*q+1], whn, hv.y);
        }
    }

    #pragma unroll
    for (int p = 0; p < 8; p++){
        #pragma unroll
        for (int hlf = 0; hlf < 2; hlf++){
            int i = 2*p + hlf;
            float rv = hlf ? hi32(ar [p]) : lo32(ar [p]);
            float zv = hlf ? hi32(az [p]) : lo32(az [p]);
            float nv = hlf ? hi32(an_[p]) : lo32(an_[p]);
            float hv = hlf ? hi32(ahn[p]) : lo32(ahn[p]);
            float r = sigmoidf_fast(rv);
            float z = sigmoidf_fast(zv);
            float nn = tanhf_fast(nv + r * hv);
            float h  = h_s[t*20 + i];
            final_out[(size_t)(n0 + i)*128 + t] = (1.0f - z)*nn + z*h;
        }
    }
}

extern "C" void kernel_launch(void* const* d_in, const int* in_sizes, int n_in,
                              void* d_out, int out_size){
    const float* atom = (const float*)d_in[0];
    const float* bond = (const float*)d_in[1];
    const int*   src  = (const int*)  d_in[2];
    // d_in[3] = dst (structurally repeat(arange(N),8); not needed)
    const float* W1  = (const float*)d_in[4];
    const float* b1  = (const float*)d_in[5];
    const float* W2  = (const float*)d_in[6];
    const float* b2  = (const float*)d_in[7];
    const float* Wa  = (const float*)d_in[8];
    const float* ba  = (const float*)d_in[9];
    const float* Ww  = (const float*)d_in[10];
    const float* bw  = (const float*)d_in[11];
    const float* Wih = (const float*)d_in[12];
    const float* bih = (const float*)d_in[13];
    const float* Whh = (const float*)d_in[14];
    const float* bhh = (const float*)d_in[15];
    float* out = (float*)d_out;

    // h1 is the 2nd output; if the harness only sized d_out for `final`,
    // keep h1 in scratch.
    float* h1_out;
    if (out_size >= 2*NNODE*FO){
        h1_out = out + (size_t)NNODE*FO;
    } else {
        void* p = nullptr;
        cudaGetSymbolAddress(&p, g_h1);
        h1_out = (float*)p;
    }

    prep_weights<<<192, 256>>>(W1, Wa, W2, Wih, Whh);
    node_kernel<<<NNODE/32, 128>>>(atom, b1, ba, Ww, h1_out);
    attn_kernel<<<NNODE/16, 128>>>(bond, src, b2, Ww, bw);
    gru_kernel <<<NNODE/16, 128>>>(bih, bhh, h1_out, out);
}